// round 11
// baseline (speedup 1.0000x reference)
#include <cuda_runtime.h>
#include <cuda_fp16.h>
#include <cstdint>

#define N_NODES 50000
#define F1 64
#define F2 128
#define F3 64
#define MAX_E 800000

// ---------------- device scratch ----------------
__device__ int     g_cnt  [N_NODES];             // in-degree; zero at entry, re-zeroed by epilogue
__device__ int2    g_ed   [MAX_E];               // packed {src, dst}
__device__ __half  g_zsh  [N_NODES * F1];        // (z * dinv) fp16 (gather src L1)
__device__ __half  g_agg1h[2 * N_NODES * F1];    // 2-way split fp16 accum L1
__device__ __half  g_h2h  [N_NODES * F3];        // (h2 * dinv) fp16 (gather src L2)
__device__ __half  g_agg2h[2 * N_NODES * F3];    // 2-way split fp16 accum L2
__device__ __half  g_w1h  [F2 * F1];             // W1^T fp16: [n][k], row stride 64
__device__ __half  g_w2h  [F3 * F2];             // W2^T fp16: [n][k], row stride 128

__device__ __forceinline__ void red4h(__half* p, uint32_t a, uint32_t b,
                                      uint32_t c, uint32_t d) {
    asm volatile("red.global.add.noftz.v4.f16x2 [%0], {%1,%2,%3,%4};"
                 :: "l"(p), "r"(a), "r"(b), "r"(c), "r"(d) : "memory");
}

__device__ __forceinline__ float rinv_of(int m) {
    return rsqrtf((float)(g_cnt[m] + 1));
}

__device__ __forceinline__ void mma16816(float* d, const uint32_t* a, const uint32_t* b) {
    asm volatile(
        "mma.sync.aligned.m16n8k16.row.col.f32.f16.f16.f32 "
        "{%0,%1,%2,%3}, {%4,%5,%6,%7}, {%8,%9}, {%0,%1,%2,%3};\n"
        : "+f"(d[0]), "+f"(d[1]), "+f"(d[2]), "+f"(d[3])
        : "r"(a[0]), "r"(a[1]), "r"(a[2]), "r"(a[3]), "r"(b[0]), "r"(b[1]));
}

__device__ __forceinline__ uint32_t cvta_smem(const void* p) {
    uint32_t a;
    asm("{ .reg .u64 t; cvta.to.shared.u64 t, %1; cvt.u32.u64 %0, t; }"
        : "=r"(a) : "l"(p));
    return a;
}

#define LDSM4(r0, r1, r2, r3, addr) \
    asm volatile("ldmatrix.sync.aligned.m8n8.x4.shared.b16 {%0,%1,%2,%3}, [%4];" \
                 : "=r"(r0), "=r"(r1), "=r"(r2), "=r"(r3) : "r"(addr))

// ------- pack edges (x2 vectorized) + degree histogram; per-block is64 detect -------
__global__ __launch_bounds__(256) void pack_deg_kernel(const void* ei, int nE) {
    __shared__ int s_is64;
    if (threadIdx.x == 0) {
        const long long* p = (const long long*)ei;
        bool ok = true;
#pragma unroll
        for (int k = 0; k < 8; k++) {
            long long v = p[k];
            if (v < 0 || v >= N_NODES) ok = false;
        }
        s_is64 = ok ? 1 : 0;      // int32 read as int64 lands out of range
    }
    __syncthreads();
    int t = blockIdx.x * 256 + threadIdx.x;      // edges 2t, 2t+1
    if (2 * t >= nE) return;
    int s0, s1, d0, d1;
    if (s_is64) {
        longlong2 sv = ((const longlong2*)ei)[t];
        longlong2 dv = *(const longlong2*)((const long long*)ei + nE + 2 * t);
        s0 = (int)sv.x; s1 = (int)sv.y; d0 = (int)dv.x; d1 = (int)dv.y;
    } else {
        int2 sv = ((const int2*)ei)[t];
        int2 dv = *(const int2*)((const int*)ei + nE + 2 * t);
        s0 = sv.x; s1 = sv.y; d0 = dv.x; d1 = dv.y;
    }
    ((int4*)g_ed)[t] = make_int4(s0, d0, s1, d1);
    atomicAdd(&g_cnt[d0], 1);
    atomicAdd(&g_cnt[d1], 1);
}

// ---- scale1 (+ fused weight convert): blocks < nbv: zsh/seed; blocks >= nbv: W->fp16^T ----
__global__ __launch_bounds__(256) void scale1_kernel(const float4* __restrict__ z4,
                                                     const float* __restrict__ W1,
                                                     const float* __restrict__ W2,
                                                     int M, int nbv) {
    if ((int)blockIdx.x >= nbv) {
        int j = (blockIdx.x - nbv) * 256 + threadIdx.x;      // 0..4095
#pragma unroll
        for (int u = 0; u < 2; u++) {
            int e = j * 2 + u;
            {   // W1 [64,128]: g_w1h[n*64+k] = W1[k*128+n]
                int k = e >> 7, n = e & 127;
                g_w1h[n * F1 + k] = __float2half(W1[k * F2 + n]);
            }
            {   // W2 [128,64]: g_w2h[n*128+k] = W2[k*64+n]
                int k = e >> 6, n = e & 63;
                g_w2h[n * F2 + k] = __float2half(W2[k * F3 + n]);
            }
        }
        return;
    }
    int i = blockIdx.x * 256 + threadIdx.x;     // over M*16 float4
    if (i >= M * 16) return;
    float r = rinv_of(i >> 4);
    float4 v = z4[i];
    __half2 h0 = __floats2half2_rn(v.x * r, v.y * r);
    __half2 h1 = __floats2half2_rn(v.z * r, v.w * r);
    __half2 zz = __floats2half2_rn(0.f, 0.f);
    ((__half2*)g_zsh)[i * 2 + 0] = h0;
    ((__half2*)g_zsh)[i * 2 + 1] = h1;
    ((__half2*)g_agg1h)[i * 2 + 0] = h0;
    ((__half2*)g_agg1h)[i * 2 + 1] = h1;
    ((__half2*)(g_agg1h + N_NODES * F1))[i * 2 + 0] = zz;
    ((__half2*)(g_agg1h + N_NODES * F1))[i * 2 + 1] = zz;
}

// ---- agg: 8 threads/edge, 16B fp16 gather, one red.v4.f16x2, parity-split dst ----
__device__ __forceinline__ void agg_body(const __half* __restrict__ src,
                                         __half* __restrict__ dst, int nE, int stride) {
    int t = blockIdx.x * 256 + threadIdx.x;
    int e = t >> 3;
    if (e >= nE) return;
    int j = t & 7;
    int2 ed = g_ed[e];
    uint4 v = ((const uint4*)src)[ed.x * 8 + j];            // 8 halves
    red4h(dst + (e & 1) * stride + ed.y * 64 + j * 8, v.x, v.y, v.z, v.w);
}

__global__ __launch_bounds__(256) void agg1_kernel(int nE) {
    agg_body(g_zsh, g_agg1h, nE, N_NODES * F1);
}

__global__ __launch_bounds__(256) void agg2_kernel(int nE) {
    agg_body(g_h2h, g_agg2h, nE, N_NODES * F3);
}

// ======== Fused GEMM1+GEMM2, 64-row tile, ldmatrix + XOR-swizzled smem ========
// smem (bytes): As 0..8K (64 rows x 128B, swz), Bs1 8K..24K (128 x 128B, swz),
//               Bs2 24K..40K (64 x 256B, swz). Xs overlays 0..16K (64 x 256B, swz).
__global__ __launch_bounds__(256) void gemm_fused(const float* __restrict__ bias1, int M) {
    __shared__ __align__(16) char smarr[40960];
    char* Asm  = smarr;
    char* Bs1m = smarr + 8192;
    char* Bs2m = smarr + 24576;
    char* Xsm  = smarr;                   // overlay (phase 2)
    uint32_t sb = cvta_smem(smarr);
    uint32_t as_b = sb, bs1_b = sb + 8192, bs2_b = sb + 24576, xs_b = sb;

    int tid  = threadIdx.x;
    int wid  = tid >> 5, lane = tid & 31;
    int g    = lane >> 2, c = lane & 3;
    int tq   = lane >> 3, tr = lane & 7;  // ldmatrix tile id / row-in-tile
    int m0   = blockIdx.x * 64;

    // Bs1: g_w1h 128 rows x 8 uint4, swizzled chunk = q ^ (n&7)
    const uint4* w1v = (const uint4*)g_w1h;
#pragma unroll
    for (int i = 0; i < 4; i++) {
        int e = tid + 256 * i;            // 0..1023
        int n = e >> 3, q = e & 7;
        *(uint4*)(Bs1m + n * 128 + ((q ^ (n & 7)) << 4)) = w1v[e];
    }
    // Bs2: g_w2h 64 rows x 16 uint4, swizzled chunk = q ^ (n&7) (bit3 kept)
    const uint4* w2v = (const uint4*)g_w2h;
#pragma unroll
    for (int i = 0; i < 4; i++) {
        int e = tid + 256 * i;            // 0..1023
        int n = e >> 4, q = e & 15;
        *(uint4*)(Bs2m + n * 256 + ((q ^ (n & 7)) << 4)) = w2v[e];
    }
    // As: (buf0+buf1)*dinv -> fp16, 64 rows x 8 uint4, swizzled
    const uint4* ag0 = (const uint4*)g_agg1h;
    const uint4* ag1 = (const uint4*)(g_agg1h + N_NODES * F1);
#pragma unroll
    for (int i = 0; i < 2; i++) {
        int e   = tid + 256 * i;          // 0..511
        int rl  = e >> 3, q = e & 7;
        int row = m0 + rl;
        uint4 o = make_uint4(0u, 0u, 0u, 0u);
        if (row < M) {
            uint4 v0 = ag0[row * 8 + q];
            uint4 v1 = ag1[row * 8 + q];
            float r  = rinv_of(row);
            const __half2* p0 = (const __half2*)&v0;
            const __half2* p1 = (const __half2*)&v1;
            __half2* po = (__half2*)&o;
#pragma unroll
            for (int u = 0; u < 4; u++) {
                float2 a = __half22float2(p0[u]);
                float2 b = __half22float2(p1[u]);
                po[u] = __floats2half2_rn((a.x + b.x) * r, (a.y + b.y) * r);
            }
        }
        *(uint4*)(Asm + rl * 128 + ((q ^ (rl & 7)) << 4)) = o;
    }
    __syncthreads();

    // ---- phase 1: 2x4 warps, warp tile 32x32, K=64 ----
    int warp_m = wid >> 2, warp_n = wid & 3;
    float d1[2][4][4];
#pragma unroll
    for (int mt = 0; mt < 2; mt++)
#pragma unroll
        for (int nt = 0; nt < 4; nt++)
#pragma unroll
            for (int u = 0; u < 4; u++) d1[mt][nt][u] = 0.f;

#pragma unroll
    for (int ks = 0; ks < 4; ks++) {
        uint32_t a[2][4], bf[4][2];
#pragma unroll
        for (int mt = 0; mt < 2; mt++) {
            int arow = warp_m * 32 + mt * 16 + (tq & 1) * 8 + tr;
            int achk = ks * 2 + (tq >> 1);
            uint32_t ad = as_b + arow * 128 + ((achk ^ (arow & 7)) << 4);
            LDSM4(a[mt][0], a[mt][1], a[mt][2], a[mt][3], ad);
        }
#pragma unroll
        for (int pr = 0; pr < 2; pr++) {
            int n    = warp_n * 32 + pr * 16 + (tq & 1) * 8 + tr;
            int bchk = ks * 2 + (tq >> 1);
            uint32_t bd = bs1_b + n * 128 + ((bchk ^ (n & 7)) << 4);
            uint32_t t0, t1, t2, t3;
            LDSM4(t0, t1, t2, t3, bd);
            bf[pr * 2 + 0][0] = t0; bf[pr * 2 + 1][0] = t1;
            bf[pr * 2 + 0][1] = t2; bf[pr * 2 + 1][1] = t3;
        }
#pragma unroll
        for (int mt = 0; mt < 2; mt++)
#pragma unroll
            for (int nt = 0; nt < 4; nt++)
                mma16816(d1[mt][nt], a[mt], bf[nt]);
    }
    __syncthreads();   // done reading As/Bs1 before Xs overwrite

    // write x = relu(d1 + bias1) into Xs (swizzled 256B rows)
#pragma unroll
    for (int nt = 0; nt < 4; nt++) {
        int n = warp_n * 32 + nt * 8 + c * 2;
        float bx = __ldg(bias1 + n), by = __ldg(bias1 + n + 1);
        int ch = n >> 3, nb = (n & 7) * 2;
#pragma unroll
        for (int mt = 0; mt < 2; mt++) {
            int rl = warp_m * 32 + mt * 16 + g;
            *(__half2*)(Xsm + rl * 256 + ((ch ^ (rl & 7)) << 4) + nb) =
                __floats2half2_rn(fmaxf(d1[mt][nt][0] + bx, 0.f),
                                  fmaxf(d1[mt][nt][1] + by, 0.f));
            int r2 = rl + 8;
            *(__half2*)(Xsm + r2 * 256 + ((ch ^ (r2 & 7)) << 4) + nb) =
                __floats2half2_rn(fmaxf(d1[mt][nt][2] + bx, 0.f),
                                  fmaxf(d1[mt][nt][3] + by, 0.f));
        }
    }
    __syncthreads();

    // ---- phase 2: 4x2 warps, warp tile 16x32, K=128 ----
    int wm2 = wid >> 1, wn2 = wid & 1;
    float d2[4][4];
#pragma unroll
    for (int nt = 0; nt < 4; nt++)
#pragma unroll
        for (int u = 0; u < 4; u++) d2[nt][u] = 0.f;

#pragma unroll
    for (int ks = 0; ks < 8; ks++) {
        uint32_t a[4], bf[4][2];
        {
            int arow = wm2 * 16 + (tq & 1) * 8 + tr;
            int achk = ks * 2 + (tq >> 1);                  // 0..15, bit3 kept by xor<=7
            uint32_t ad = xs_b + arow * 256 + ((achk ^ (arow & 7)) << 4);
            LDSM4(a[0], a[1], a[2], a[3], ad);
        }
#pragma unroll
        for (int pr = 0; pr < 2; pr++) {
            int n    = wn2 * 32 + pr * 16 + (tq & 1) * 8 + tr;
            int bchk = ks * 2 + (tq >> 1);
            uint32_t bd = bs2_b + n * 256 + ((bchk ^ (n & 7)) << 4);
            uint32_t t0, t1, t2, t3;
            LDSM4(t0, t1, t2, t3, bd);
            bf[pr * 2 + 0][0] = t0; bf[pr * 2 + 1][0] = t1;
            bf[pr * 2 + 0][1] = t2; bf[pr * 2 + 1][1] = t3;
        }
#pragma unroll
        for (int nt = 0; nt < 4; nt++)
            mma16816(d2[nt], a, bf[nt]);
    }

    // epilogue: v = d2*dinv -> h2h, agg2 buf0 seed; buf1 = 0
    __half2* h2h = (__half2*)g_h2h;
    __half2* s0  = (__half2*)g_agg2h;
    __half2* s1  = (__half2*)(g_agg2h + N_NODES * F3);
    __half2 zz = __floats2half2_rn(0.f, 0.f);
#pragma unroll
    for (int hr = 0; hr < 2; hr++) {
        int row = m0 + wm2 * 16 + g + hr * 8;
        if (row >= M) continue;
        float r = rinv_of(row);
#pragma unroll
        for (int nt = 0; nt < 4; nt++) {
            int n = wn2 * 32 + nt * 8 + c * 2;
            __half2 h = __floats2half2_rn(d2[nt][hr * 2 + 0] * r,
                                          d2[nt][hr * 2 + 1] * r);
            int idx = row * 32 + (n >> 1);
            h2h[idx] = h;
            s0[idx]  = h;
            s1[idx]  = zz;
        }
    }
}

// ------- epilogue: out = relu((buf0+buf1)*dinv + b2); then zero g_cnt for next run -------
__global__ __launch_bounds__(256) void epilogue_kernel(const float* __restrict__ b2,
                                                       float* __restrict__ out, int M) {
    int i = blockIdx.x * 256 + threadIdx.x;     // over M*8 uint4-of-halves
    bool act = i < M * 8;
    int m = 0, c = 0;
    float r = 0.f;
    uint4 v0, v1;
    if (act) {
        m = i >> 3; c = i & 7;
        r = rinv_of(m);                          // read g_cnt BEFORE zeroing
        v0 = ((const uint4*)g_agg2h)[i];
        v1 = ((const uint4*)(g_agg2h + N_NODES * F3))[i];
    }
    __syncthreads();
    if (!act) return;
    float2 a0 = __half22float2(*(const __half2*)&v0.x);
    float2 a1 = __half22float2(*(const __half2*)&v0.y);
    float2 a2 = __half22float2(*(const __half2*)&v0.z);
    float2 a3 = __half22float2(*(const __half2*)&v0.w);
    float2 c0 = __half22float2(*(const __half2*)&v1.x);
    float2 c1 = __half22float2(*(const __half2*)&v1.y);
    float2 c2 = __half22float2(*(const __half2*)&v1.z);
    float2 c3 = __half22float2(*(const __half2*)&v1.w);
    float4 blo = *(const float4*)(b2 + c * 8);
    float4 bhi = *(const float4*)(b2 + c * 8 + 4);
    float4 o0, o1;
    o0.x = fmaxf((a0.x + c0.x) * r + blo.x, 0.f);
    o0.y = fmaxf((a0.y + c0.y) * r + blo.y, 0.f);
    o0.z = fmaxf((a1.x + c1.x) * r + blo.z, 0.f);
    o0.w = fmaxf((a1.y + c1.y) * r + blo.w, 0.f);
    o1.x = fmaxf((a2.x + c2.x) * r + bhi.x, 0.f);
    o1.y = fmaxf((a2.y + c2.y) * r + bhi.y, 0.f);
    o1.z = fmaxf((a3.x + c3.x) * r + bhi.z, 0.f);
    o1.w = fmaxf((a3.y + c3.y) * r + bhi.w, 0.f);
    ((float4*)out)[i * 2 + 0] = o0;
    ((float4*)out)[i * 2 + 1] = o1;
    if ((i & 7) == 0) g_cnt[m] = 0;              // reset for next (re)play
}

// ---------------- launch ----------------
extern "C" void kernel_launch(void* const* d_in, const int* in_sizes, int n_in,
                              void* d_out, int out_size) {
    const float* z  = (const float*)d_in[0];
    const void*  ei = d_in[1];
    const float* W1 = (const float*)d_in[2];
    const float* b1 = (const float*)d_in[3];
    const float* W2 = (const float*)d_in[4];
    const float* b2 = (const float*)d_in[5];
    float* out = (float*)d_out;

    int nE = in_sizes[1] / 2;
    int M  = in_sizes[0] / F1;

    int nb_pack = (nE / 2 + 255) / 256;
    int nb_agg  = (nE * 8 + 255) / 256;
    int nb_vec  = (M * 16 + 255) / 256;
    int nb_epi  = (M * 8 + 255) / 256;
    int nb_tc   = (M + 63) / 64;

    pack_deg_kernel<<<nb_pack, 256>>>(ei, nE);
    scale1_kernel<<<nb_vec + 16, 256>>>((const float4*)z, W1, W2, M, nb_vec);
    agg1_kernel<<<nb_agg, 256>>>(nE);
    gemm_fused<<<nb_tc, 256>>>(b1, M);
    agg2_kernel<<<nb_agg, 256>>>(nE);
    epilogue_kernel<<<nb_epi, 256>>>(b2, out, M);
}

// round 12
// speedup vs baseline: 1.0040x; 1.0040x over previous
#include <cuda_runtime.h>
#include <cuda_fp16.h>
#include <cstdint>

#define N_NODES 50000
#define F1 64
#define F2 128
#define F3 64
#define MAX_E 800000

// ---------------- device scratch ----------------
__device__ int     g_cnt  [N_NODES];             // in-degree; zero at entry, re-zeroed by epilogue
__device__ int2    g_ed   [MAX_E];               // packed {src, dst}
__device__ __half  g_zsh  [N_NODES * F1];        // (z * dinv) fp16 (gather src L1)
__device__ __half  g_agg1h[2 * N_NODES * F1];    // 2-way split fp16 accum L1
__device__ __half  g_h2h  [N_NODES * F3];        // (h2 * dinv) fp16 (gather src L2)
__device__ __half  g_agg2h[2 * N_NODES * F3];    // 2-way split fp16 accum L2
__device__ __half  g_w1h  [F2 * F1];             // W1^T fp16: [n][k], row stride 64
__device__ __half  g_w2h  [F3 * F2];             // W2^T fp16: [n][k], row stride 128

__device__ __forceinline__ void red4h(__half* p, uint32_t a, uint32_t b,
                                      uint32_t c, uint32_t d) {
    asm volatile("red.global.add.noftz.v4.f16x2 [%0], {%1,%2,%3,%4};"
                 :: "l"(p), "r"(a), "r"(b), "r"(c), "r"(d) : "memory");
}

__device__ __forceinline__ float rinv_of(int m) {
    return rsqrtf((float)(g_cnt[m] + 1));
}

__device__ __forceinline__ void mma16816(float* d, const uint32_t* a, const uint32_t* b) {
    asm volatile(
        "mma.sync.aligned.m16n8k16.row.col.f32.f16.f16.f32 "
        "{%0,%1,%2,%3}, {%4,%5,%6,%7}, {%8,%9}, {%0,%1,%2,%3};\n"
        : "+f"(d[0]), "+f"(d[1]), "+f"(d[2]), "+f"(d[3])
        : "r"(a[0]), "r"(a[1]), "r"(a[2]), "r"(a[3]), "r"(b[0]), "r"(b[1]));
}

__device__ __forceinline__ uint32_t cvta_smem(const void* p) {
    uint32_t a;
    asm("{ .reg .u64 t; cvta.to.shared.u64 t, %1; cvt.u32.u64 %0, t; }"
        : "=r"(a) : "l"(p));
    return a;
}

#define LDSM4(r0, r1, r2, r3, addr) \
    asm volatile("ldmatrix.sync.aligned.m8n8.x4.shared.b16 {%0,%1,%2,%3}, [%4];" \
                 : "=r"(r0), "=r"(r1), "=r"(r2), "=r"(r3) : "r"(addr))

// ------- pack edges (x2 vectorized) + degree histogram; per-block is64 detect -------
__global__ __launch_bounds__(256) void pack_deg_kernel(const void* ei, int nE) {
    __shared__ int s_is64;
    if (threadIdx.x == 0) {
        const long long* p = (const long long*)ei;
        bool ok = true;
#pragma unroll
        for (int k = 0; k < 8; k++) {
            long long v = p[k];
            if (v < 0 || v >= N_NODES) ok = false;
        }
        s_is64 = ok ? 1 : 0;      // int32 read as int64 lands out of range
    }
    __syncthreads();
    int t = blockIdx.x * 256 + threadIdx.x;      // edges 2t, 2t+1
    if (2 * t >= nE) return;
    int s0, s1, d0, d1;
    if (s_is64) {
        longlong2 sv = ((const longlong2*)ei)[t];
        longlong2 dv = *(const longlong2*)((const long long*)ei + nE + 2 * t);
        s0 = (int)sv.x; s1 = (int)sv.y; d0 = (int)dv.x; d1 = (int)dv.y;
    } else {
        int2 sv = ((const int2*)ei)[t];
        int2 dv = *(const int2*)((const int*)ei + nE + 2 * t);
        s0 = sv.x; s1 = sv.y; d0 = dv.x; d1 = dv.y;
    }
    ((int4*)g_ed)[t] = make_int4(s0, d0, s1, d1);
    atomicAdd(&g_cnt[d0], 1);
    atomicAdd(&g_cnt[d1], 1);
}

// ---- scale1 (+ fused weight convert): blocks < nbv: zsh/seed; blocks >= nbv: W->fp16^T ----
__global__ __launch_bounds__(256) void scale1_kernel(const float4* __restrict__ z4,
                                                     const float* __restrict__ W1,
                                                     const float* __restrict__ W2,
                                                     int M, int nbv) {
    if ((int)blockIdx.x >= nbv) {
        int j = (blockIdx.x - nbv) * 256 + threadIdx.x;      // 0..4095
#pragma unroll
        for (int u = 0; u < 2; u++) {
            int e = j * 2 + u;
            {   // W1 [64,128]: g_w1h[n*64+k] = W1[k*128+n]
                int k = e >> 7, n = e & 127;
                g_w1h[n * F1 + k] = __float2half(W1[k * F2 + n]);
            }
            {   // W2 [128,64]: g_w2h[n*128+k] = W2[k*64+n]
                int k = e >> 6, n = e & 63;
                g_w2h[n * F2 + k] = __float2half(W2[k * F3 + n]);
            }
        }
        return;
    }
    int i = blockIdx.x * 256 + threadIdx.x;     // over M*16 float4
    if (i >= M * 16) return;
    float r = rinv_of(i >> 4);
    float4 v = z4[i];
    __half2 h0 = __floats2half2_rn(v.x * r, v.y * r);
    __half2 h1 = __floats2half2_rn(v.z * r, v.w * r);
    __half2 zz = __floats2half2_rn(0.f, 0.f);
    ((__half2*)g_zsh)[i * 2 + 0] = h0;
    ((__half2*)g_zsh)[i * 2 + 1] = h1;
    ((__half2*)g_agg1h)[i * 2 + 0] = h0;
    ((__half2*)g_agg1h)[i * 2 + 1] = h1;
    ((__half2*)(g_agg1h + N_NODES * F1))[i * 2 + 0] = zz;
    ((__half2*)(g_agg1h + N_NODES * F1))[i * 2 + 1] = zz;
}

// ---- agg: 8 threads/edge, 16B fp16 gather, one red.v4.f16x2, parity-split dst ----
__device__ __forceinline__ void agg_body(const __half* __restrict__ src,
                                         __half* __restrict__ dst, int nE, int stride) {
    int t = blockIdx.x * 256 + threadIdx.x;
    int e = t >> 3;
    if (e >= nE) return;
    int j = t & 7;
    int2 ed = g_ed[e];
    uint4 v = ((const uint4*)src)[ed.x * 8 + j];            // 8 halves
    red4h(dst + (e & 1) * stride + ed.y * 64 + j * 8, v.x, v.y, v.z, v.w);
}

__global__ __launch_bounds__(256) void agg1_kernel(int nE) {
    agg_body(g_zsh, g_agg1h, nE, N_NODES * F1);
}

__global__ __launch_bounds__(256) void agg2_kernel(int nE) {
    agg_body(g_h2h, g_agg2h, nE, N_NODES * F3);
}

// ======== Fused GEMM1+GEMM2, 128-row tile, 512 threads, 2 CTAs/SM ========
// smem (bytes): As 0..16K (128 x 128B, swz), Bs1 16K..32K (128 x 128B, swz),
//               Bs2 32K..48K (64 x 256B, swz). Xs overlays 0..32K (128 x 256B, swz).
__global__ __launch_bounds__(512, 2) void gemm_fused(const float* __restrict__ bias1, int M) {
    __shared__ __align__(16) char smarr[49152];
    char* Asm  = smarr;
    char* Bs1m = smarr + 16384;
    char* Bs2m = smarr + 32768;
    char* Xsm  = smarr;                   // overlay (phase 2)
    uint32_t sb = cvta_smem(smarr);
    uint32_t as_b = sb, bs1_b = sb + 16384, bs2_b = sb + 32768, xs_b = sb;

    int tid  = threadIdx.x;
    int wid  = tid >> 5, lane = tid & 31;
    int g    = lane >> 2, c = lane & 3;
    int tq   = lane >> 3, tr = lane & 7;  // ldmatrix tile id / row-in-tile
    int m0   = blockIdx.x * 128;

    // As: (buf0+buf1)*dinv -> fp16, 128 rows x 8 uint4, swizzled (issued first)
    const uint4* ag0 = (const uint4*)g_agg1h;
    const uint4* ag1 = (const uint4*)(g_agg1h + N_NODES * F1);
#pragma unroll
    for (int i = 0; i < 2; i++) {
        int e   = tid + 512 * i;          // 0..1023
        int rl  = e >> 3, q = e & 7;
        int row = m0 + rl;
        uint4 o = make_uint4(0u, 0u, 0u, 0u);
        if (row < M) {
            uint4 v0 = ag0[row * 8 + q];
            uint4 v1 = ag1[row * 8 + q];
            float r  = rinv_of(row);
            const __half2* p0 = (const __half2*)&v0;
            const __half2* p1 = (const __half2*)&v1;
            __half2* po = (__half2*)&o;
#pragma unroll
            for (int u = 0; u < 4; u++) {
                float2 a = __half22float2(p0[u]);
                float2 b = __half22float2(p1[u]);
                po[u] = __floats2half2_rn((a.x + b.x) * r, (a.y + b.y) * r);
            }
        }
        *(uint4*)(Asm + rl * 128 + ((q ^ (rl & 7)) << 4)) = o;
    }
    // Bs1: g_w1h 128 rows x 8 uint4, swizzled chunk = q ^ (n&7)
    const uint4* w1v = (const uint4*)g_w1h;
#pragma unroll
    for (int i = 0; i < 2; i++) {
        int e = tid + 512 * i;            // 0..1023
        int n = e >> 3, q = e & 7;
        *(uint4*)(Bs1m + n * 128 + ((q ^ (n & 7)) << 4)) = w1v[e];
    }
    // Bs2: g_w2h 64 rows x 16 uint4, swizzled chunk = q ^ (n&7)
    const uint4* w2v = (const uint4*)g_w2h;
#pragma unroll
    for (int i = 0; i < 2; i++) {
        int e = tid + 512 * i;            // 0..1023
        int n = e >> 4, q = e & 15;
        *(uint4*)(Bs2m + n * 256 + ((q ^ (n & 7)) << 4)) = w2v[e];
    }
    __syncthreads();

    // ---- phase 1: 4x4 warps, warp tile 32x32, K=64 ----
    int warp_m = wid >> 2, warp_n = wid & 3;
    float d1[2][4][4];
#pragma unroll
    for (int mt = 0; mt < 2; mt++)
#pragma unroll
        for (int nt = 0; nt < 4; nt++)
#pragma unroll
            for (int u = 0; u < 4; u++) d1[mt][nt][u] = 0.f;

#pragma unroll
    for (int ks = 0; ks < 4; ks++) {
        uint32_t a[2][4], bf[4][2];
#pragma unroll
        for (int mt = 0; mt < 2; mt++) {
            int arow = warp_m * 32 + mt * 16 + (tq & 1) * 8 + tr;
            int achk = ks * 2 + (tq >> 1);
            uint32_t ad = as_b + arow * 128 + ((achk ^ (arow & 7)) << 4);
            LDSM4(a[mt][0], a[mt][1], a[mt][2], a[mt][3], ad);
        }
#pragma unroll
        for (int pr = 0; pr < 2; pr++) {
            int n    = warp_n * 32 + pr * 16 + (tq & 1) * 8 + tr;
            int bchk = ks * 2 + (tq >> 1);
            uint32_t bd = bs1_b + n * 128 + ((bchk ^ (n & 7)) << 4);
            uint32_t t0, t1, t2, t3;
            LDSM4(t0, t1, t2, t3, bd);
            bf[pr * 2 + 0][0] = t0; bf[pr * 2 + 1][0] = t1;
            bf[pr * 2 + 0][1] = t2; bf[pr * 2 + 1][1] = t3;
        }
#pragma unroll
        for (int mt = 0; mt < 2; mt++)
#pragma unroll
            for (int nt = 0; nt < 4; nt++)
                mma16816(d1[mt][nt], a[mt], bf[nt]);
    }
    __syncthreads();   // done reading As/Bs1 before Xs overwrite

    // write x = relu(d1 + bias1) into Xs (swizzled 256B rows)
#pragma unroll
    for (int nt = 0; nt < 4; nt++) {
        int n = warp_n * 32 + nt * 8 + c * 2;
        float bx = __ldg(bias1 + n), by = __ldg(bias1 + n + 1);
        int ch = n >> 3, nb = (n & 7) * 2;
#pragma unroll
        for (int mt = 0; mt < 2; mt++) {
            int rl = warp_m * 32 + mt * 16 + g;
            *(__half2*)(Xsm + rl * 256 + ((ch ^ (rl & 7)) << 4) + nb) =
                __floats2half2_rn(fmaxf(d1[mt][nt][0] + bx, 0.f),
                                  fmaxf(d1[mt][nt][1] + by, 0.f));
            int r2 = rl + 8;
            *(__half2*)(Xsm + r2 * 256 + ((ch ^ (r2 & 7)) << 4) + nb) =
                __floats2half2_rn(fmaxf(d1[mt][nt][2] + bx, 0.f),
                                  fmaxf(d1[mt][nt][3] + by, 0.f));
        }
    }
    __syncthreads();

    // ---- phase 2: 8x2 warps, warp tile 16x32, K=128 ----
    int wm2 = wid >> 1, wn2 = wid & 1;
    float d2[4][4];
#pragma unroll
    for (int nt = 0; nt < 4; nt++)
#pragma unroll
        for (int u = 0; u < 4; u++) d2[nt][u] = 0.f;

#pragma unroll
    for (int ks = 0; ks < 8; ks++) {
        uint32_t a[4], bf[4][2];
        {
            int arow = wm2 * 16 + (tq & 1) * 8 + tr;
            int achk = ks * 2 + (tq >> 1);
            uint32_t ad = xs_b + arow * 256 + ((achk ^ (arow & 7)) << 4);
            LDSM4(a[0], a[1], a[2], a[3], ad);
        }
#pragma unroll
        for (int pr = 0; pr < 2; pr++) {
            int n    = wn2 * 32 + pr * 16 + (tq & 1) * 8 + tr;
            int bchk = ks * 2 + (tq >> 1);
            uint32_t bd = bs2_b + n * 256 + ((bchk ^ (n & 7)) << 4);
            uint32_t t0, t1, t2, t3;
            LDSM4(t0, t1, t2, t3, bd);
            bf[pr * 2 + 0][0] = t0; bf[pr * 2 + 1][0] = t1;
            bf[pr * 2 + 0][1] = t2; bf[pr * 2 + 1][1] = t3;
        }
#pragma unroll
        for (int nt = 0; nt < 4; nt++)
            mma16816(d2[nt], a, bf[nt]);
    }

    // epilogue: v = d2*dinv -> h2h, agg2 buf0 seed; buf1 = 0
    __half2* h2h = (__half2*)g_h2h;
    __half2* s0  = (__half2*)g_agg2h;
    __half2* s1  = (__half2*)(g_agg2h + N_NODES * F3);
    __half2 zz = __floats2half2_rn(0.f, 0.f);
#pragma unroll
    for (int hr = 0; hr < 2; hr++) {
        int row = m0 + wm2 * 16 + g + hr * 8;
        if (row >= M) continue;
        float r = rinv_of(row);
#pragma unroll
        for (int nt = 0; nt < 4; nt++) {
            int n = wn2 * 32 + nt * 8 + c * 2;
            __half2 h = __floats2half2_rn(d2[nt][hr * 2 + 0] * r,
                                          d2[nt][hr * 2 + 1] * r);
            int idx = row * 32 + (n >> 1);
            h2h[idx] = h;
            s0[idx]  = h;
            s1[idx]  = zz;
        }
    }
}

// ------- epilogue: out = relu((buf0+buf1)*dinv + b2); then zero g_cnt for next run -------
__global__ __launch_bounds__(256) void epilogue_kernel(const float* __restrict__ b2,
                                                       float* __restrict__ out, int M) {
    int i = blockIdx.x * 256 + threadIdx.x;     // over M*8 uint4-of-halves
    bool act = i < M * 8;
    int m = 0, c = 0;
    float r = 0.f;
    uint4 v0, v1;
    if (act) {
        m = i >> 3; c = i & 7;
        r = rinv_of(m);                          // read g_cnt BEFORE zeroing
        v0 = ((const uint4*)g_agg2h)[i];
        v1 = ((const uint4*)(g_agg2h + N_NODES * F3))[i];
    }
    __syncthreads();
    if (!act) return;
    float2 a0 = __half22float2(*(const __half2*)&v0.x);
    float2 a1 = __half22float2(*(const __half2*)&v0.y);
    float2 a2 = __half22float2(*(const __half2*)&v0.z);
    float2 a3 = __half22float2(*(const __half2*)&v0.w);
    float2 c0 = __half22float2(*(const __half2*)&v1.x);
    float2 c1 = __half22float2(*(const __half2*)&v1.y);
    float2 c2 = __half22float2(*(const __half2*)&v1.z);
    float2 c3 = __half22float2(*(const __half2*)&v1.w);
    float4 blo = *(const float4*)(b2 + c * 8);
    float4 bhi = *(const float4*)(b2 + c * 8 + 4);
    float4 o0, o1;
    o0.x = fmaxf((a0.x + c0.x) * r + blo.x, 0.f);
    o0.y = fmaxf((a0.y + c0.y) * r + blo.y, 0.f);
    o0.z = fmaxf((a1.x + c1.x) * r + blo.z, 0.f);
    o0.w = fmaxf((a1.y + c1.y) * r + blo.w, 0.f);
    o1.x = fmaxf((a2.x + c2.x) * r + bhi.x, 0.f);
    o1.y = fmaxf((a2.y + c2.y) * r + bhi.y, 0.f);
    o1.z = fmaxf((a3.x + c3.x) * r + bhi.z, 0.f);
    o1.w = fmaxf((a3.y + c3.y) * r + bhi.w, 0.f);
    ((float4*)out)[i * 2 + 0] = o0;
    ((float4*)out)[i * 2 + 1] = o1;
    if ((i & 7) == 0) g_cnt[m] = 0;              // reset for next (re)play
}

// ---------------- launch ----------------
extern "C" void kernel_launch(void* const* d_in, const int* in_sizes, int n_in,
                              void* d_out, int out_size) {
    const float* z  = (const float*)d_in[0];
    const void*  ei = d_in[1];
    const float* W1 = (const float*)d_in[2];
    const float* b1 = (const float*)d_in[3];
    const float* W2 = (const float*)d_in[4];
    const float* b2 = (const float*)d_in[5];
    float* out = (float*)d_out;

    int nE = in_sizes[1] / 2;
    int M  = in_sizes[0] / F1;

    int nb_pack = (nE / 2 + 255) / 256;
    int nb_agg  = (nE * 8 + 255) / 256;
    int nb_vec  = (M * 16 + 255) / 256;
    int nb_epi  = (M * 8 + 255) / 256;
    int nb_tc   = (M + 127) / 128;

    pack_deg_kernel<<<nb_pack, 256>>>(ei, nE);
    scale1_kernel<<<nb_vec + 16, 256>>>((const float4*)z, W1, W2, M, nb_vec);
    agg1_kernel<<<nb_agg, 256>>>(nE);
    gemm_fused<<<nb_tc, 512>>>(b1, M);
    agg2_kernel<<<nb_agg, 256>>>(nE);
    epilogue_kernel<<<nb_epi, 256>>>(b2, out, M);
}

// round 14
// speedup vs baseline: 1.0207x; 1.0166x over previous
#include <cuda_runtime.h>
#include <cuda_fp16.h>
#include <cstdint>

#define N_NODES 50000
#define F1 64
#define F2 128
#define F3 64
#define MAX_E 800000

// ---------------- device scratch ----------------
__device__ int     g_cnt  [N_NODES];             // in-degree; zero at entry, re-zeroed by epilogue
__device__ int2    g_ed   [MAX_E];               // packed {src, dst}
__device__ __half  g_zsh  [N_NODES * F1];        // (z * dinv) fp16 (gather src L1)
__device__ __half  g_agg1h[2 * N_NODES * F1];    // 2-way split fp16 accum L1
__device__ __half  g_h2h  [N_NODES * F3];        // (h2 * dinv) fp16 (gather src L2 + self term)
__device__ __half  g_agg2h[2 * N_NODES * F3];    // 2-way split fp16 accum L2 (zeroed in scale1)
__device__ __half  g_w1h  [F2 * F1];             // W1^T fp16: [n][k], row stride 64
__device__ __half  g_w2h  [F3 * F2];             // W2^T fp16: [n][k], row stride 128

__device__ __forceinline__ void red4h(__half* p, uint32_t a, uint32_t b,
                                      uint32_t c, uint32_t d) {
    asm volatile("red.global.add.noftz.v4.f16x2 [%0], {%1,%2,%3,%4};"
                 :: "l"(p), "r"(a), "r"(b), "r"(c), "r"(d) : "memory");
}

__device__ __forceinline__ float rinv_of(int m) {
    return rsqrtf((float)(g_cnt[m] + 1));
}

__device__ __forceinline__ void mma16816(float* d, const uint32_t* a, const uint32_t* b) {
    asm volatile(
        "mma.sync.aligned.m16n8k16.row.col.f32.f16.f16.f32 "
        "{%0,%1,%2,%3}, {%4,%5,%6,%7}, {%8,%9}, {%0,%1,%2,%3};\n"
        : "+f"(d[0]), "+f"(d[1]), "+f"(d[2]), "+f"(d[3])
        : "r"(a[0]), "r"(a[1]), "r"(a[2]), "r"(a[3]), "r"(b[0]), "r"(b[1]));
}

__device__ __forceinline__ uint32_t cvta_smem(const void* p) {
    uint32_t a;
    asm("{ .reg .u64 t; cvta.to.shared.u64 t, %1; cvt.u32.u64 %0, t; }"
        : "=r"(a) : "l"(p));
    return a;
}

#define LDSM4(r0, r1, r2, r3, addr) \
    asm volatile("ldmatrix.sync.aligned.m8n8.x4.shared.b16 {%0,%1,%2,%3}, [%4];" \
                 : "=r"(r0), "=r"(r1), "=r"(r2), "=r"(r3) : "r"(addr))

// ------- pack edges (x2 vectorized) + degree histogram; per-block is64 detect -------
__global__ __launch_bounds__(256) void pack_deg_kernel(const void* ei, int nE) {
    __shared__ int s_is64;
    if (threadIdx.x == 0) {
        const long long* p = (const long long*)ei;
        bool ok = true;
#pragma unroll
        for (int k = 0; k < 8; k++) {
            long long v = p[k];
            if (v < 0 || v >= N_NODES) ok = false;
        }
        s_is64 = ok ? 1 : 0;      // int32 read as int64 lands out of range
    }
    __syncthreads();
    int t = blockIdx.x * 256 + threadIdx.x;      // edges 2t, 2t+1
    if (2 * t >= nE) return;
    int s0, s1, d0, d1;
    if (s_is64) {
        longlong2 sv = ((const longlong2*)ei)[t];
        longlong2 dv = *(const longlong2*)((const long long*)ei + nE + 2 * t);
        s0 = (int)sv.x; s1 = (int)sv.y; d0 = (int)dv.x; d1 = (int)dv.y;
    } else {
        int2 sv = ((const int2*)ei)[t];
        int2 dv = *(const int2*)((const int*)ei + nE + 2 * t);
        s0 = sv.x; s1 = sv.y; d0 = dv.x; d1 = dv.y;
    }
    ((int4*)g_ed)[t] = make_int4(s0, d0, s1, d1);
    atomicAdd(&g_cnt[d0], 1);
    atomicAdd(&g_cnt[d1], 1);
}

// ---- scale1: zsh/agg1 seeds + zero agg2 bufs; tail blocks convert W->fp16^T ----
__global__ __launch_bounds__(256) void scale1_kernel(const float4* __restrict__ z4,
                                                     const float* __restrict__ W1,
                                                     const float* __restrict__ W2,
                                                     int M, int nbv) {
    if ((int)blockIdx.x >= nbv) {
        int j = (blockIdx.x - nbv) * 256 + threadIdx.x;      // 0..4095
#pragma unroll
        for (int u = 0; u < 2; u++) {
            int e = j * 2 + u;
            {   // W1 [64,128]: g_w1h[n*64+k] = W1[k*128+n]
                int k = e >> 7, n = e & 127;
                g_w1h[n * F1 + k] = __float2half(W1[k * F2 + n]);
            }
            {   // W2 [128,64]: g_w2h[n*128+k] = W2[k*64+n]
                int k = e >> 6, n = e & 63;
                g_w2h[n * F2 + k] = __float2half(W2[k * F3 + n]);
            }
        }
        return;
    }
    int i = blockIdx.x * 256 + threadIdx.x;     // over M*16 float4
    if (i >= M * 16) return;
    float r = rinv_of(i >> 4);
    float4 v = z4[i];
    __half2 h0 = __floats2half2_rn(v.x * r, v.y * r);
    __half2 h1 = __floats2half2_rn(v.z * r, v.w * r);
    __half2 zz = __floats2half2_rn(0.f, 0.f);
    ((__half2*)g_zsh)[i * 2 + 0] = h0;
    ((__half2*)g_zsh)[i * 2 + 1] = h1;
    ((__half2*)g_agg1h)[i * 2 + 0] = h0;
    ((__half2*)g_agg1h)[i * 2 + 1] = h1;
    ((__half2*)(g_agg1h + N_NODES * F1))[i * 2 + 0] = zz;
    ((__half2*)(g_agg1h + N_NODES * F1))[i * 2 + 1] = zz;
    if (i < M * 8) {                             // zero both agg2 buffers (uint4 each)
        uint4 z4v = make_uint4(0u, 0u, 0u, 0u);
        ((uint4*)g_agg2h)[i] = z4v;
        ((uint4*)(g_agg2h + N_NODES * F3))[i] = z4v;
    }
}

// ---- agg: 8 threads/edge, 16B fp16 gather, one red.v4.f16x2, parity-split dst ----
__device__ __forceinline__ void agg_body(const __half* __restrict__ src,
                                         __half* __restrict__ dst, int nE, int stride) {
    int t = blockIdx.x * 256 + threadIdx.x;
    int e = t >> 3;
    if (e >= nE) return;
    int j = t & 7;
    int2 ed = g_ed[e];
    uint4 v = ((const uint4*)src)[ed.x * 8 + j];            // 8 halves
    red4h(dst + (e & 1) * stride + ed.y * 64 + j * 8, v.x, v.y, v.z, v.w);
}

__global__ __launch_bounds__(256) void agg1_kernel(int nE) {
    agg_body(g_zsh, g_agg1h, nE, N_NODES * F1);
}

__global__ __launch_bounds__(256) void agg2_kernel(int nE) {
    agg_body(g_h2h, g_agg2h, nE, N_NODES * F3);
}

// ======== Fused GEMM1+GEMM2, 128-row tile, 512 threads, 2 CTAs/SM ========
// smem: As 0..16K (128x128B swz), Bs1 16K..32K (128x128B swz), Bs2 32K..48K (64x256B swz)
// Xs overlays 0..32K (128x256B swz); staging overlays 0..18.4K (128 x 144B rows)
__global__ __launch_bounds__(512, 2) void gemm_fused(const float* __restrict__ bias1, int M) {
    __shared__ __align__(16) char smarr[49152];
    char* Asm  = smarr;
    char* Bs1m = smarr + 16384;
    char* Bs2m = smarr + 32768;
    char* Xsm  = smarr;                   // overlay (phase 2)
    char* Stg  = smarr;                   // overlay (epilogue staging, 128x144B)
    uint32_t sb = cvta_smem(smarr);
    uint32_t as_b = sb, bs1_b = sb + 16384, bs2_b = sb + 32768, xs_b = sb;

    int tid  = threadIdx.x;
    int wid  = tid >> 5, lane = tid & 31;
    int g    = lane >> 2, c = lane & 3;
    int tq   = lane >> 3, tr = lane & 7;  // ldmatrix tile id / row-in-tile
    int m0   = blockIdx.x * 128;

    // As: (buf0+buf1)*dinv -> fp16, 128 rows x 8 uint4, swizzled
    const uint4* ag0 = (const uint4*)g_agg1h;
    const uint4* ag1 = (const uint4*)(g_agg1h + N_NODES * F1);
#pragma unroll
    for (int i = 0; i < 2; i++) {
        int e   = tid + 512 * i;          // 0..1023
        int rl  = e >> 3, q = e & 7;
        int row = m0 + rl;
        uint4 o = make_uint4(0u, 0u, 0u, 0u);
        if (row < M) {
            uint4 v0 = ag0[row * 8 + q];
            uint4 v1 = ag1[row * 8 + q];
            float r  = rinv_of(row);
            const __half2* p0 = (const __half2*)&v0;
            const __half2* p1 = (const __half2*)&v1;
            __half2* po = (__half2*)&o;
#pragma unroll
            for (int u = 0; u < 4; u++) {
                float2 a = __half22float2(p0[u]);
                float2 b = __half22float2(p1[u]);
                po[u] = __floats2half2_rn((a.x + b.x) * r, (a.y + b.y) * r);
            }
        }
        *(uint4*)(Asm + rl * 128 + ((q ^ (rl & 7)) << 4)) = o;
    }
    // Bs1: g_w1h 128 rows x 8 uint4
    const uint4* w1v = (const uint4*)g_w1h;
#pragma unroll
    for (int i = 0; i < 2; i++) {
        int e = tid + 512 * i;
        int n = e >> 3, q = e & 7;
        *(uint4*)(Bs1m + n * 128 + ((q ^ (n & 7)) << 4)) = w1v[e];
    }
    // Bs2: g_w2h 64 rows x 16 uint4
    const uint4* w2v = (const uint4*)g_w2h;
#pragma unroll
    for (int i = 0; i < 2; i++) {
        int e = tid + 512 * i;
        int n = e >> 4, q = e & 15;
        *(uint4*)(Bs2m + n * 256 + ((q ^ (n & 7)) << 4)) = w2v[e];
    }
    __syncthreads();

    // ---- phase 1: 4x4 warps, warp tile 32x32, K=64 ----
    int warp_m = wid >> 2, warp_n = wid & 3;
    float d1[2][4][4];
#pragma unroll
    for (int mt = 0; mt < 2; mt++)
#pragma unroll
        for (int nt = 0; nt < 4; nt++)
#pragma unroll
            for (int u = 0; u < 4; u++) d1[mt][nt][u] = 0.f;

#pragma unroll
    for (int ks = 0; ks < 4; ks++) {
        uint32_t a[2][4], bf[4][2];
#pragma unroll
        for (int mt = 0; mt < 2; mt++) {
            int arow = warp_m * 32 + mt * 16 + (tq & 1) * 8 + tr;
            int achk = ks * 2 + (tq >> 1);
            uint32_t ad = as_b + arow * 128 + ((achk ^ (arow & 7)) << 4);
            LDSM4(a[mt][0], a[mt][1], a[mt][2], a[mt][3], ad);
        }
#pragma unroll
        for (int pr = 0; pr < 2; pr++) {
            int n    = warp_n * 32 + pr * 16 + (tq & 1) * 8 + tr;
            int bchk = ks * 2 + (tq >> 1);
            uint32_t bd = bs1_b + n * 128 + ((bchk ^ (n & 7)) << 4);
            uint32_t t0, t1, t2, t3;
            LDSM4(t0, t1, t2, t3, bd);
            bf[pr * 2 + 0][0] = t0; bf[pr * 2 + 1][0] = t1;
            bf[pr * 2 + 0][1] = t2; bf[pr * 2 + 1][1] = t3;
        }
#pragma unroll
        for (int mt = 0; mt < 2; mt++)
#pragma unroll
            for (int nt = 0; nt < 4; nt++)
                mma16816(d1[mt][nt], a[mt], bf[nt]);
    }
    __syncthreads();   // done reading As/Bs1 before Xs overwrite

    // write x = relu(d1 + bias1) into Xs (swizzled 256B rows)
#pragma unroll
    for (int nt = 0; nt < 4; nt++) {
        int n = warp_n * 32 + nt * 8 + c * 2;
        float bx = __ldg(bias1 + n), by = __ldg(bias1 + n + 1);
        int ch = n >> 3, nb = (n & 7) * 2;
#pragma unroll
        for (int mt = 0; mt < 2; mt++) {
            int rl = warp_m * 32 + mt * 16 + g;
            *(__half2*)(Xsm + rl * 256 + ((ch ^ (rl & 7)) << 4) + nb) =
                __floats2half2_rn(fmaxf(d1[mt][nt][0] + bx, 0.f),
                                  fmaxf(d1[mt][nt][1] + by, 0.f));
            int r2 = rl + 8;
            *(__half2*)(Xsm + r2 * 256 + ((ch ^ (r2 & 7)) << 4) + nb) =
                __floats2half2_rn(fmaxf(d1[mt][nt][2] + bx, 0.f),
                                  fmaxf(d1[mt][nt][3] + by, 0.f));
        }
    }
    __syncthreads();

    // ---- phase 2: 8x2 warps, warp tile 16x32, K=128 ----
    int wm2 = wid >> 1, wn2 = wid & 1;
    float d2[4][4];
#pragma unroll
    for (int nt = 0; nt < 4; nt++)
#pragma unroll
        for (int u = 0; u < 4; u++) d2[nt][u] = 0.f;

#pragma unroll
    for (int ks = 0; ks < 8; ks++) {
        uint32_t a[4], bf[4][2];
        {
            int arow = wm2 * 16 + (tq & 1) * 8 + tr;
            int achk = ks * 2 + (tq >> 1);
            uint32_t ad = xs_b + arow * 256 + ((achk ^ (arow & 7)) << 4);
            LDSM4(a[0], a[1], a[2], a[3], ad);
        }
#pragma unroll
        for (int pr = 0; pr < 2; pr++) {
            int n    = wn2 * 32 + pr * 16 + (tq & 1) * 8 + tr;
            int bchk = ks * 2 + (tq >> 1);
            uint32_t bd = bs2_b + n * 256 + ((bchk ^ (n & 7)) << 4);
            uint32_t t0, t1, t2, t3;
            LDSM4(t0, t1, t2, t3, bd);
            bf[pr * 2 + 0][0] = t0; bf[pr * 2 + 1][0] = t1;
            bf[pr * 2 + 0][1] = t2; bf[pr * 2 + 1][1] = t3;
        }
#pragma unroll
        for (int nt = 0; nt < 4; nt++)
            mma16816(d2[nt], a, bf[nt]);
    }
    __syncthreads();   // done reading Xs before staging overwrite

    // stage v = half2(d2*dinv) into Stg (144B row stride)
#pragma unroll
    for (int hr = 0; hr < 2; hr++) {
        int rl  = wm2 * 16 + g + hr * 8;
        int row = m0 + rl;
        float r = (row < M) ? rinv_of(row) : 0.f;
#pragma unroll
        for (int nt = 0; nt < 4; nt++) {
            int n = wn2 * 32 + nt * 8 + c * 2;
            *(__half2*)(Stg + rl * 144 + n * 2) =
                __floats2half2_rn(d2[nt][hr * 2 + 0] * r, d2[nt][hr * 2 + 1] * r);
        }
    }
    __syncthreads();

    // vectorized store: h2h (gather src for agg2 + self term for final epilogue)
    uint4* h2v = (uint4*)g_h2h;
#pragma unroll
    for (int i = 0; i < 2; i++) {
        int e   = tid * 2 + i;            // 0..1023 over 128 rows x 8 uint4
        int rl  = e >> 3, q = e & 7;
        int row = m0 + rl;
        if (row < M)
            h2v[row * 8 + q] = *(const uint4*)(Stg + rl * 144 + q * 16);
    }
}

// ------- epilogue: out = relu((s0+s1+h2h)*dinv + b2); then zero g_cnt for next run -------
__global__ __launch_bounds__(256) void epilogue_kernel(const float* __restrict__ b2,
                                                       float* __restrict__ out, int M) {
    int i = blockIdx.x * 256 + threadIdx.x;     // over M*8 uint4-of-halves
    bool act = i < M * 8;
    int m = 0, c = 0;
    float r = 0.f;
    uint4 v0, v1, v2;
    if (act) {
        m = i >> 3; c = i & 7;
        r = rinv_of(m);                          // read g_cnt BEFORE zeroing
        v0 = ((const uint4*)g_agg2h)[i];
        v1 = ((const uint4*)(g_agg2h + N_NODES * F3))[i];
        v2 = ((const uint4*)g_h2h)[i];           // self-loop term
    }
    __syncthreads();
    if (!act) return;
    const __half2* p0 = (const __half2*)&v0;
    const __half2* p1 = (const __half2*)&v1;
    const __half2* p2 = (const __half2*)&v2;
    float4 blo = *(const float4*)(b2 + c * 8);
    float4 bhi = *(const float4*)(b2 + c * 8 + 4);

    float2 a0 = __half22float2(p0[0]), b0 = __half22float2(p1[0]), h0 = __half22float2(p2[0]);
    float2 a1 = __half22float2(p0[1]), b1 = __half22float2(p1[1]), h1 = __half22float2(p2[1]);
    float2 a2 = __half22float2(p0[2]), b2v = __half22float2(p1[2]), h2 = __half22float2(p2[2]);
    float2 a3 = __half22float2(p0[3]), b3 = __half22float2(p1[3]), h3 = __half22float2(p2[3]);
    float4 o0, o1;
    o0.x = fmaxf((a0.x + b0.x + h0.x) * r + blo.x, 0.f);
    o0.y = fmaxf((a0.y + b0.y + h0.y) * r + blo.y, 0.f);
    o0.z = fmaxf((a1.x + b1.x + h1.x) * r + blo.z, 0.f);
    o0.w = fmaxf((a1.y + b1.y + h1.y) * r + blo.w, 0.f);
    o1.x = fmaxf((a2.x + b2v.x + h2.x) * r + bhi.x, 0.f);
    o1.y = fmaxf((a2.y + b2v.y + h2.y) * r + bhi.y, 0.f);
    o1.z = fmaxf((a3.x + b3.x + h3.x) * r + bhi.z, 0.f);
    o1.w = fmaxf((a3.y + b3.y + h3.y) * r + bhi.w, 0.f);
    ((float4*)out)[i * 2 + 0] = o0;
    ((float4*)out)[i * 2 + 1] = o1;
    if ((i & 7) == 0) g_cnt[m] = 0;              // reset for next (re)play
}

// ---------------- launch ----------------
extern "C" void kernel_launch(void* const* d_in, const int* in_sizes, int n_in,
                              void* d_out, int out_size) {
    const float* z  = (const float*)d_in[0];
    const void*  ei = d_in[1];
    const float* W1 = (const float*)d_in[2];
    const float* b1 = (const float*)d_in[3];
    const float* W2 = (const float*)d_in[4];
    const float* b2 = (const float*)d_in[5];
    float* out = (float*)d_out;

    int nE = in_sizes[1] / 2;
    int M  = in_sizes[0] / F1;

    int nb_pack = (nE / 2 + 255) / 256;
    int nb_agg  = (nE * 8 + 255) / 256;
    int nb_vec  = (M * 16 + 255) / 256;
    int nb_epi  = (M * 8 + 255) / 256;
    int nb_tc   = (M + 127) / 128;

    pack_deg_kernel<<<nb_pack, 256>>>(ei, nE);
    scale1_kernel<<<nb_vec + 16, 256>>>((const float4*)z, W1, W2, M, nb_vec);
    agg1_kernel<<<nb_agg, 256>>>(nE);
    gemm_fused<<<nb_tc, 512>>>(b1, M);
    agg2_kernel<<<nb_agg, 256>>>(nE);
    epilogue_kernel<<<nb_epi, 256>>>(b2, out, M);
}

// round 15
// speedup vs baseline: 1.0282x; 1.0074x over previous
#include <cuda_runtime.h>
#include <cuda_fp16.h>
#include <cstdint>

#define N_NODES 50000
#define F1 64
#define F2 128
#define F3 64
#define MAX_E 800000

// ---------------- device scratch ----------------
__device__ int     g_cnt  [N_NODES];             // in-degree; zero at entry, re-zeroed by epilogue
__device__ int2    g_ed   [MAX_E];               // packed {src, dst}
__device__ __half  g_zsh  [N_NODES * F1];        // (z * dinv) fp16 (gather src L1)
__device__ __half  g_agg1h[2 * N_NODES * F1];    // 2-way split fp16 accum L1
__device__ __half  g_h2h  [N_NODES * F3];        // (h2 * dinv) fp16 (gather src L2 + self term)
__device__ __half  g_agg2h[2 * N_NODES * F3];    // 2-way split fp16 accum L2 (zeroed in pack_deg)
__device__ __half  g_w1h  [F2 * F1];             // W1^T fp16: [n][k], row stride 64
__device__ __half  g_w2h  [F3 * F2];             // W2^T fp16: [n][k], row stride 128

__device__ __forceinline__ void red4h(__half* p, uint32_t a, uint32_t b,
                                      uint32_t c, uint32_t d) {
    asm volatile("red.global.add.noftz.v4.f16x2 [%0], {%1,%2,%3,%4};"
                 :: "l"(p), "r"(a), "r"(b), "r"(c), "r"(d) : "memory");
}

__device__ __forceinline__ float rinv_of(int m) {
    return rsqrtf((float)(g_cnt[m] + 1));
}

__device__ __forceinline__ void mma16816(float* d, const uint32_t* a, const uint32_t* b) {
    asm volatile(
        "mma.sync.aligned.m16n8k16.row.col.f32.f16.f16.f32 "
        "{%0,%1,%2,%3}, {%4,%5,%6,%7}, {%8,%9}, {%0,%1,%2,%3};\n"
        : "+f"(d[0]), "+f"(d[1]), "+f"(d[2]), "+f"(d[3])
        : "r"(a[0]), "r"(a[1]), "r"(a[2]), "r"(a[3]), "r"(b[0]), "r"(b[1]));
}

__device__ __forceinline__ uint32_t cvta_smem(const void* p) {
    uint32_t a;
    asm("{ .reg .u64 t; cvta.to.shared.u64 t, %1; cvt.u32.u64 %0, t; }"
        : "=r"(a) : "l"(p));
    return a;
}

#define LDSM4(r0, r1, r2, r3, addr) \
    asm volatile("ldmatrix.sync.aligned.m8n8.x4.shared.b16 {%0,%1,%2,%3}, [%4];" \
                 : "=r"(r0), "=r"(r1), "=r"(r2), "=r"(r3) : "r"(addr))

#define CP_ASYNC16(saddr, gptr) \
    asm volatile("cp.async.cg.shared.global [%0], [%1], 16;" \
                 :: "r"(saddr), "l"(gptr) : "memory")
#define CP_ASYNC_COMMIT() asm volatile("cp.async.commit_group;" ::: "memory")
#define CP_ASYNC_WAIT0()  asm volatile("cp.async.wait_group 0;" ::: "memory")

// ------- pack edges (x2 vectorized) + degree histogram + agg2 zero-fill -------
__global__ __launch_bounds__(256) void pack_deg_kernel(const void* ei, int nE, int M) {
    __shared__ int s_is64;
    if (threadIdx.x == 0) {
        const long long* p = (const long long*)ei;
        bool ok = true;
#pragma unroll
        for (int k = 0; k < 8; k++) {
            long long v = p[k];
            if (v < 0 || v >= N_NODES) ok = false;
        }
        s_is64 = ok ? 1 : 0;      // int32 read as int64 lands out of range
    }
    __syncthreads();
    int t = blockIdx.x * 256 + threadIdx.x;
    if (t < M * 8) {                             // zero both agg2 buffers (uint4 each)
        uint4 z4v = make_uint4(0u, 0u, 0u, 0u);
        ((uint4*)g_agg2h)[t] = z4v;
        ((uint4*)(g_agg2h + N_NODES * F3))[t] = z4v;
    }
    if (2 * t >= nE) return;                     // edges 2t, 2t+1
    int s0, s1, d0, d1;
    if (s_is64) {
        longlong2 sv = ((const longlong2*)ei)[t];
        longlong2 dv = *(const longlong2*)((const long long*)ei + nE + 2 * t);
        s0 = (int)sv.x; s1 = (int)sv.y; d0 = (int)dv.x; d1 = (int)dv.y;
    } else {
        int2 sv = ((const int2*)ei)[t];
        int2 dv = *(const int2*)((const int*)ei + nE + 2 * t);
        s0 = sv.x; s1 = sv.y; d0 = dv.x; d1 = dv.y;
    }
    ((int4*)g_ed)[t] = make_int4(s0, d0, s1, d1);
    atomicAdd(&g_cnt[d0], 1);
    atomicAdd(&g_cnt[d1], 1);
}

// ---- scale1: zsh/agg1 seeds; tail blocks convert W->fp16^T ----
__global__ __launch_bounds__(256) void scale1_kernel(const float4* __restrict__ z4,
                                                     const float* __restrict__ W1,
                                                     const float* __restrict__ W2,
                                                     int M, int nbv) {
    if ((int)blockIdx.x >= nbv) {
        int j = (blockIdx.x - nbv) * 256 + threadIdx.x;      // 0..4095
#pragma unroll
        for (int u = 0; u < 2; u++) {
            int e = j * 2 + u;
            {   // W1 [64,128]: g_w1h[n*64+k] = W1[k*128+n]
                int k = e >> 7, n = e & 127;
                g_w1h[n * F1 + k] = __float2half(W1[k * F2 + n]);
            }
            {   // W2 [128,64]: g_w2h[n*128+k] = W2[k*64+n]
                int k = e >> 6, n = e & 63;
                g_w2h[n * F2 + k] = __float2half(W2[k * F3 + n]);
            }
        }
        return;
    }
    int i = blockIdx.x * 256 + threadIdx.x;     // over M*16 float4
    if (i >= M * 16) return;
    float r = rinv_of(i >> 4);
    float4 v = z4[i];
    __half2 h0 = __floats2half2_rn(v.x * r, v.y * r);
    __half2 h1 = __floats2half2_rn(v.z * r, v.w * r);
    __half2 zz = __floats2half2_rn(0.f, 0.f);
    ((__half2*)g_zsh)[i * 2 + 0] = h0;
    ((__half2*)g_zsh)[i * 2 + 1] = h1;
    ((__half2*)g_agg1h)[i * 2 + 0] = h0;
    ((__half2*)g_agg1h)[i * 2 + 1] = h1;
    ((__half2*)(g_agg1h + N_NODES * F1))[i * 2 + 0] = zz;
    ((__half2*)(g_agg1h + N_NODES * F1))[i * 2 + 1] = zz;
}

// ---- agg: 8 threads/edge, 16B fp16 gather, one red.v4.f16x2, parity-split dst ----
__device__ __forceinline__ void agg_body(const __half* __restrict__ src,
                                         __half* __restrict__ dst, int nE, int stride) {
    int t = blockIdx.x * 256 + threadIdx.x;
    int e = t >> 3;
    if (e >= nE) return;
    int j = t & 7;
    int2 ed = g_ed[e];
    uint4 v = ((const uint4*)src)[ed.x * 8 + j];            // 8 halves
    red4h(dst + (e & 1) * stride + ed.y * 64 + j * 8, v.x, v.y, v.z, v.w);
}

__global__ __launch_bounds__(256) void agg1_kernel(int nE) {
    agg_body(g_zsh, g_agg1h, nE, N_NODES * F1);
}

__global__ __launch_bounds__(256) void agg2_kernel(int nE) {
    agg_body(g_h2h, g_agg2h, nE, N_NODES * F3);
}

// ======== Fused GEMM1+GEMM2, 128-row tile, 512 threads, 2 CTAs/SM ========
// smem: As 0..16K (128x128B swz), Bs1 16K..32K (128x128B swz), Bs2 32K..48K (64x256B swz)
// Xs overlays 0..32K (128x256B swz); staging overlays 0..18.4K (128 x 144B rows)
__global__ __launch_bounds__(512, 2) void gemm_fused(const float* __restrict__ bias1, int M) {
    __shared__ __align__(16) char smarr[49152];
    char* Asm  = smarr;
    char* Xsm  = smarr;                   // overlay (phase 2)
    char* Stg  = smarr;                   // overlay (epilogue staging, 128x144B)
    uint32_t sb = cvta_smem(smarr);
    uint32_t as_b = sb, bs1_b = sb + 16384, bs2_b = sb + 32768, xs_b = sb;

    int tid  = threadIdx.x;
    int wid  = tid >> 5, lane = tid & 31;
    int g    = lane >> 2, c = lane & 3;
    int tq   = lane >> 3, tr = lane & 7;  // ldmatrix tile id / row-in-tile
    int m0   = blockIdx.x * 128;

    // weights via cp.async (pure copies — off the register chain)
    const uint4* w1v = (const uint4*)g_w1h;
    const uint4* w2v = (const uint4*)g_w2h;
#pragma unroll
    for (int i = 0; i < 2; i++) {
        int e = tid + 512 * i;            // 0..1023
        {   // Bs1: 128 rows x 8 uint4
            int n = e >> 3, q = e & 7;
            CP_ASYNC16(bs1_b + n * 128 + ((q ^ (n & 7)) << 4), w1v + e);
        }
        {   // Bs2: 64 rows x 16 uint4
            int n = e >> 4, q = e & 15;
            CP_ASYNC16(bs2_b + n * 256 + ((q ^ (n & 7)) << 4), w2v + e);
        }
    }
    CP_ASYNC_COMMIT();

    // As: (buf0+buf1)*dinv -> fp16 (half2 math), 128 rows x 8 uint4, swizzled
    const uint4* ag0 = (const uint4*)g_agg1h;
    const uint4* ag1 = (const uint4*)(g_agg1h + N_NODES * F1);
#pragma unroll
    for (int i = 0; i < 2; i++) {
        int e   = tid + 512 * i;          // 0..1023
        int rl  = e >> 3, q = e & 7;
        int row = m0 + rl;
        uint4 o = make_uint4(0u, 0u, 0u, 0u);
        if (row < M) {
            uint4 v0 = ag0[row * 8 + q];
            uint4 v1 = ag1[row * 8 + q];
            __half2 rh = __float2half2_rn(rinv_of(row));
            const __half2* p0 = (const __half2*)&v0;
            const __half2* p1 = (const __half2*)&v1;
            __half2* po = (__half2*)&o;
#pragma unroll
            for (int u = 0; u < 4; u++)
                po[u] = __hmul2(__hadd2(p0[u], p1[u]), rh);
        }
        *(uint4*)(Asm + rl * 128 + ((q ^ (rl & 7)) << 4)) = o;
    }
    CP_ASYNC_WAIT0();
    __syncthreads();

    // ---- phase 1: 4x4 warps, warp tile 32x32, K=64 ----
    int warp_m = wid >> 2, warp_n = wid & 3;
    float d1[2][4][4];
#pragma unroll
    for (int mt = 0; mt < 2; mt++)
#pragma unroll
        for (int nt = 0; nt < 4; nt++)
#pragma unroll
            for (int u = 0; u < 4; u++) d1[mt][nt][u] = 0.f;

#pragma unroll
    for (int ks = 0; ks < 4; ks++) {
        uint32_t a[2][4], bf[4][2];
#pragma unroll
        for (int mt = 0; mt < 2; mt++) {
            int arow = warp_m * 32 + mt * 16 + (tq & 1) * 8 + tr;
            int achk = ks * 2 + (tq >> 1);
            uint32_t ad = as_b + arow * 128 + ((achk ^ (arow & 7)) << 4);
            LDSM4(a[mt][0], a[mt][1], a[mt][2], a[mt][3], ad);
        }
#pragma unroll
        for (int pr = 0; pr < 2; pr++) {
            int n    = warp_n * 32 + pr * 16 + (tq & 1) * 8 + tr;
            int bchk = ks * 2 + (tq >> 1);
            uint32_t bd = bs1_b + n * 128 + ((bchk ^ (n & 7)) << 4);
            uint32_t t0, t1, t2, t3;
            LDSM4(t0, t1, t2, t3, bd);
            bf[pr * 2 + 0][0] = t0; bf[pr * 2 + 1][0] = t1;
            bf[pr * 2 + 0][1] = t2; bf[pr * 2 + 1][1] = t3;
        }
#pragma unroll
        for (int mt = 0; mt < 2; mt++)
#pragma unroll
            for (int nt = 0; nt < 4; nt++)
                mma16816(d1[mt][nt], a[mt], bf[nt]);
    }
    __syncthreads();   // done reading As/Bs1 before Xs overwrite

    // write x = relu(d1 + bias1) into Xs (swizzled 256B rows)
#pragma unroll
    for (int nt = 0; nt < 4; nt++) {
        int n = warp_n * 32 + nt * 8 + c * 2;
        float bx = __ldg(bias1 + n), by = __ldg(bias1 + n + 1);
        int ch = n >> 3, nb = (n & 7) * 2;
#pragma unroll
        for (int mt = 0; mt < 2; mt++) {
            int rl = warp_m * 32 + mt * 16 + g;
            *(__half2*)(Xsm + rl * 256 + ((ch ^ (rl & 7)) << 4) + nb) =
                __floats2half2_rn(fmaxf(d1[mt][nt][0] + bx, 0.f),
                                  fmaxf(d1[mt][nt][1] + by, 0.f));
            int r2 = rl + 8;
            *(__half2*)(Xsm + r2 * 256 + ((ch ^ (r2 & 7)) << 4) + nb) =
                __floats2half2_rn(fmaxf(d1[mt][nt][2] + bx, 0.f),
                                  fmaxf(d1[mt][nt][3] + by, 0.f));
        }
    }
    __syncthreads();

    // ---- phase 2: 8x2 warps, warp tile 16x32, K=128 ----
    int wm2 = wid >> 1, wn2 = wid & 1;
    float d2[4][4];
#pragma unroll
    for (int nt = 0; nt < 4; nt++)
#pragma unroll
        for (int u = 0; u < 4; u++) d2[nt][u] = 0.f;

#pragma unroll
    for (int ks = 0; ks < 8; ks++) {
        uint32_t a[4], bf[4][2];
        {
            int arow = wm2 * 16 + (tq & 1) * 8 + tr;
            int achk = ks * 2 + (tq >> 1);
            uint32_t ad = xs_b + arow * 256 + ((achk ^ (arow & 7)) << 4);
            LDSM4(a[0], a[1], a[2], a[3], ad);
        }
#pragma unroll
        for (int pr = 0; pr < 2; pr++) {
            int n    = wn2 * 32 + pr * 16 + (tq & 1) * 8 + tr;
            int bchk = ks * 2 + (tq >> 1);
            uint32_t bd = bs2_b + n * 256 + ((bchk ^ (n & 7)) << 4);
            uint32_t t0, t1, t2, t3;
            LDSM4(t0, t1, t2, t3, bd);
            bf[pr * 2 + 0][0] = t0; bf[pr * 2 + 1][0] = t1;
            bf[pr * 2 + 0][1] = t2; bf[pr * 2 + 1][1] = t3;
        }
#pragma unroll
        for (int nt = 0; nt < 4; nt++)
            mma16816(d2[nt], a, bf[nt]);
    }
    __syncthreads();   // done reading Xs before staging overwrite

    // stage v = half2(d2*dinv) into Stg (144B row stride)
#pragma unroll
    for (int hr = 0; hr < 2; hr++) {
        int rl  = wm2 * 16 + g + hr * 8;
        int row = m0 + rl;
        float r = (row < M) ? rinv_of(row) : 0.f;
#pragma unroll
        for (int nt = 0; nt < 4; nt++) {
            int n = wn2 * 32 + nt * 8 + c * 2;
            *(__half2*)(Stg + rl * 144 + n * 2) =
                __floats2half2_rn(d2[nt][hr * 2 + 0] * r, d2[nt][hr * 2 + 1] * r);
        }
    }
    __syncthreads();

    // vectorized store: h2h (gather src for agg2 + self term for final epilogue)
    uint4* h2v = (uint4*)g_h2h;
#pragma unroll
    for (int i = 0; i < 2; i++) {
        int e   = tid * 2 + i;            // 0..1023 over 128 rows x 8 uint4
        int rl  = e >> 3, q = e & 7;
        int row = m0 + rl;
        if (row < M)
            h2v[row * 8 + q] = *(const uint4*)(Stg + rl * 144 + q * 16);
    }
}

// ------- epilogue: out = relu((s0+s1+h2h)*dinv + b2); then zero g_cnt for next run -------
__global__ __launch_bounds__(256) void epilogue_kernel(const float* __restrict__ b2,
                                                       float* __restrict__ out, int M) {
    int i = blockIdx.x * 256 + threadIdx.x;     // over M*8 uint4-of-halves
    bool act = i < M * 8;
    int m = 0, c = 0;
    float r = 0.f;
    uint4 v0, v1, v2;
    if (act) {
        m = i >> 3; c = i & 7;
        r = rinv_of(m);                          // read g_cnt BEFORE zeroing
        v0 = ((const uint4*)g_agg2h)[i];
        v1 = ((const uint4*)(g_agg2h + N_NODES * F3))[i];
        v2 = ((const uint4*)g_h2h)[i];           // self-loop term
    }
    __syncthreads();
    if (!act) return;
    const __half2* p0 = (const __half2*)&v0;
    const __half2* p1 = (const __half2*)&v1;
    const __half2* p2 = (const __half2*)&v2;
    float4 blo = *(const float4*)(b2 + c * 8);
    float4 bhi = *(const float4*)(b2 + c * 8 + 4);

    float2 a0 = __half22float2(p0[0]), b0 = __half22float2(p1[0]), h0 = __half22float2(p2[0]);
    float2 a1 = __half22float2(p0[1]), b1 = __half22float2(p1[1]), h1 = __half22float2(p2[1]);
    float2 a2 = __half22float2(p0[2]), b2v = __half22float2(p1[2]), h2 = __half22float2(p2[2]);
    float2 a3 = __half22float2(p0[3]), b3 = __half22float2(p1[3]), h3 = __half22float2(p2[3]);
    float4 o0, o1;
    o0.x = fmaxf((a0.x + b0.x + h0.x) * r + blo.x, 0.f);
    o0.y = fmaxf((a0.y + b0.y + h0.y) * r + blo.y, 0.f);
    o0.z = fmaxf((a1.x + b1.x + h1.x) * r + blo.z, 0.f);
    o0.w = fmaxf((a1.y + b1.y + h1.y) * r + blo.w, 0.f);
    o1.x = fmaxf((a2.x + b2v.x + h2.x) * r + bhi.x, 0.f);
    o1.y = fmaxf((a2.y + b2v.y + h2.y) * r + bhi.y, 0.f);
    o1.z = fmaxf((a3.x + b3.x + h3.x) * r + bhi.z, 0.f);
    o1.w = fmaxf((a3.y + b3.y + h3.y) * r + bhi.w, 0.f);
    ((float4*)out)[i * 2 + 0] = o0;
    ((float4*)out)[i * 2 + 1] = o1;
    if ((i & 7) == 0) g_cnt[m] = 0;              // reset for next (re)play
}

// ---------------- launch ----------------
extern "C" void kernel_launch(void* const* d_in, const int* in_sizes, int n_in,
                              void* d_out, int out_size) {
    const float* z  = (const float*)d_in[0];
    const void*  ei = d_in[1];
    const float* W1 = (const float*)d_in[2];
    const float* b1 = (const float*)d_in[3];
    const float* W2 = (const float*)d_in[4];
    const float* b2 = (const float*)d_in[5];
    float* out = (float*)d_out;

    int nE = in_sizes[1] / 2;
    int M  = in_sizes[0] / F1;

    int nb_pack_e = (nE / 2 + 255) / 256;
    int nb_pack_z = (M * 8 + 255) / 256;
    int nb_pack   = nb_pack_e > nb_pack_z ? nb_pack_e : nb_pack_z;
    int nb_agg  = (nE * 8 + 255) / 256;
    int nb_vec  = (M * 16 + 255) / 256;
    int nb_epi  = (M * 8 + 255) / 256;
    int nb_tc   = (M + 127) / 128;

    pack_deg_kernel<<<nb_pack, 256>>>(ei, nE, M);
    scale1_kernel<<<nb_vec + 16, 256>>>((const float4*)z, W1, W2, M, nb_vec);
    agg1_kernel<<<nb_agg, 256>>>(nE);
    gemm_fused<<<nb_tc, 512>>>(b1, M);
    agg2_kernel<<<nb_agg, 256>>>(nE);
    epilogue_kernel<<<nb_epi, 256>>>(b2, out, M);
}